// round 17
// baseline (speedup 1.0000x reference)
#include <cuda_runtime.h>
#include <cuda_bf16.h>
#include <math.h>

#define T_SEQ 2048
#define C_DIM 1024
#define HEADS 16
#define KV_HEADS 4
#define HDIM 64
#define KV_DIM 512
#define WINDOW_SZ 512

typedef unsigned long long ull;

// ---------------- scratch (no cudaMalloc allowed) ----------------
__device__ float g_q[T_SEQ * C_DIM];
__device__ float g_kv[T_SEQ * KV_DIM];

__device__ __nv_bfloat16 g_xh[T_SEQ * C_DIM], g_xl[T_SEQ * C_DIM];
// Wq (1024 rows) and Wkv (512 rows) concatenated: [1536 x 1024]
__device__ __nv_bfloat16 g_wqkh[1536 * C_DIM], g_wqkl[1536 * C_DIM];
__device__ __nv_bfloat16 g_wph[C_DIM * C_DIM], g_wpl[C_DIM * C_DIM];
__device__ __nv_bfloat16 g_yh[T_SEQ * C_DIM], g_yl[T_SEQ * C_DIM];
__device__ __nv_bfloat16 g_qh[T_SEQ * C_DIM], g_ql[T_SEQ * C_DIM];
__device__ __nv_bfloat16 g_kvh[T_SEQ * KV_DIM], g_kvl[T_SEQ * KV_DIM];

// ---------------- PTX helpers (baseline-arch: sm_80/75 era) ----------------
__device__ __forceinline__ unsigned smem_u32(const void* p) {
    unsigned a;
    asm("{ .reg .u64 t; cvta.to.shared.u64 t, %1; cvt.u32.u64 %0, t; }"
        : "=r"(a) : "l"(p));
    return a;
}
__device__ __forceinline__ void cp_async16(unsigned dst, const void* src) {
    asm volatile("cp.async.cg.shared.global [%0], [%1], 16;\n"
                 :: "r"(dst), "l"(src) : "memory");
}
__device__ __forceinline__ void ldm4(unsigned addr, unsigned& r0, unsigned& r1,
                                     unsigned& r2, unsigned& r3) {
    asm volatile("ldmatrix.sync.aligned.m8n8.x4.shared.b16 {%0,%1,%2,%3}, [%4];"
                 : "=r"(r0), "=r"(r1), "=r"(r2), "=r"(r3) : "r"(addr));
}
__device__ __forceinline__ void ldm4t(unsigned addr, unsigned& r0, unsigned& r1,
                                      unsigned& r2, unsigned& r3) {
    asm volatile("ldmatrix.sync.aligned.m8n8.x4.trans.shared.b16 {%0,%1,%2,%3}, [%4];"
                 : "=r"(r0), "=r"(r1), "=r"(r2), "=r"(r3) : "r"(addr));
}
__device__ __forceinline__ void mma16816(float* c, const unsigned* a,
                                         unsigned b0, unsigned b1) {
    asm volatile("mma.sync.aligned.m16n8k16.row.col.f32.bf16.bf16.f32 "
                 "{%0,%1,%2,%3}, {%4,%5,%6,%7}, {%8,%9}, {%0,%1,%2,%3};"
                 : "+f"(c[0]), "+f"(c[1]), "+f"(c[2]), "+f"(c[3])
                 : "r"(a[0]), "r"(a[1]), "r"(a[2]), "r"(a[3]), "r"(b0), "r"(b1));
}
__device__ __forceinline__ void split2(float x, float y, unsigned& hi, unsigned& lo) {
    __nv_bfloat16 hx = __float2bfloat16(x), hy = __float2bfloat16(y);
    __nv_bfloat16 lx = __float2bfloat16(x - __bfloat162float(hx));
    __nv_bfloat16 ly = __float2bfloat16(y - __bfloat162float(hy));
    hi = (unsigned)__bfloat16_as_ushort(hx) | ((unsigned)__bfloat16_as_ushort(hy) << 16);
    lo = (unsigned)__bfloat16_as_ushort(lx) | ((unsigned)__bfloat16_as_ushort(ly) << 16);
}

// ---------------------------------------------------------------------------
// Combined hi/lo split of all four fp32 inputs, ONE launch, 2 float4/thread,
// 16B hi/lo stores. All range sizes are even (in float4 units) so a pair
// never straddles a range boundary.
// ---------------------------------------------------------------------------
__global__ __launch_bounds__(256)
void cvt_split4(const float* __restrict__ s0, __nv_bfloat16* h0, __nv_bfloat16* l0, int n0,
                const float* __restrict__ s1, __nv_bfloat16* h1, __nv_bfloat16* l1, int n1,
                const float* __restrict__ s2, __nv_bfloat16* h2, __nv_bfloat16* l2, int n2,
                const float* __restrict__ s3, __nv_bfloat16* h3, __nv_bfloat16* l3, int n3)
{
    int p = blockIdx.x * blockDim.x + threadIdx.x;
    int j = 2 * p;
    const float* in; __nv_bfloat16 *hi, *lo;
    if (j < n0)              { in = s0; hi = h0; lo = l0; }
    else if ((j -= n0) < n1) { in = s1; hi = h1; lo = l1; }
    else if ((j -= n1) < n2) { in = s2; hi = h2; lo = l2; }
    else if ((j -= n2) < n3) { in = s3; hi = h3; lo = l3; }
    else return;

    float4 v0 = reinterpret_cast<const float4*>(in)[j];
    float4 v1 = reinterpret_cast<const float4*>(in)[j + 1];
    unsigned ha, hb, hc, hd, la, lb, lc, ld;
    split2(v0.x, v0.y, ha, la);
    split2(v0.z, v0.w, hb, lb);
    split2(v1.x, v1.y, hc, lc);
    split2(v1.z, v1.w, hd, ld);
    reinterpret_cast<uint4*>(hi)[p - (blockIdx.x * blockDim.x + threadIdx.x) + j / 2] =
        make_uint4(ha, hb, hc, hd);
    reinterpret_cast<uint4*>(lo)[j / 2] = make_uint4(la, lb, lc, ld);
}

// ---------------------------------------------------------------------------
// HMMA split-bf16 GEMM: C[M,N] = A*B^T, 3-stage cp.async pipeline.
// Output split: tiles with n0 < nsplit -> C0 (ld Nld0), else C1 (ld Nld1).
// ---------------------------------------------------------------------------
#define CHUNK_BYTES 32768

__global__ __launch_bounds__(256, 2)
void gemm_tc(const __nv_bfloat16* __restrict__ Ah, const __nv_bfloat16* __restrict__ Al,
             const __nv_bfloat16* __restrict__ Bh, const __nv_bfloat16* __restrict__ Bl,
             float* __restrict__ C0, float* __restrict__ C1,
             int nsplit, int Nld0, int Nld1)
{
    extern __shared__ __align__(16) unsigned char dsmem[];
    const unsigned sbase = smem_u32(dsmem);

    const int tid = threadIdx.x;
    const int lane = tid & 31, wid = tid >> 5;
    const int m0 = blockIdx.y * 128, n0 = blockIdx.x * 128;
    const int warp_m = (wid & 1) * 64, warp_n = (wid >> 1) * 32;

    const int arow = lane & 15, aoff = lane >> 4;
    const int brow = (lane & 7) + ((lane >> 4) << 3);
    const int boff = (lane >> 3) & 1;

    float acc[4][4][4];
#pragma unroll
    for (int mf = 0; mf < 4; mf++)
#pragma unroll
        for (int nf = 0; nf < 4; nf++)
#pragma unroll
            for (int r = 0; r < 4; r++) acc[mf][nf][r] = 0.f;

    auto fill = [&](int kc, unsigned bufbase) {
#pragma unroll
        for (int i = 0; i < 8; i++) {
            int idx = tid + i * 256;
            int tile = idx >> 9;
            int e = idx & 511;
            int r = e >> 2, c = e & 3;
            const __nv_bfloat16* srcb =
                (tile == 0) ? Ah : (tile == 1) ? Al : (tile == 2) ? Bh : Bl;
            int row = ((tile < 2) ? m0 : n0) + r;
            const __nv_bfloat16* src = srcb + (size_t)row * 1024 + kc * 32 + c * 8;
            unsigned dst = bufbase + tile * 8192 + r * 64 + (((c + (r >> 1)) & 3) << 4);
            cp_async16(dst, src);
        }
        asm volatile("cp.async.commit_group;\n" ::: "memory");
    };

    fill(0, sbase);
    fill(1, sbase + CHUNK_BYTES);

    for (int kc = 0; kc < 32; kc++) {
        const unsigned cur = sbase + (kc % 3) * CHUNK_BYTES;
        if (kc + 2 < 32) {
            fill(kc + 2, sbase + ((kc + 2) % 3) * CHUNK_BYTES);
            asm volatile("cp.async.wait_group 2;\n" ::: "memory");
        } else if (kc + 1 < 32) {
            asm volatile("cp.async.wait_group 1;\n" ::: "memory");
        } else {
            asm volatile("cp.async.wait_group 0;\n" ::: "memory");
        }
        __syncthreads();

        const unsigned aH = cur, aL = cur + 8192, bH = cur + 16384, bL = cur + 24576;
#pragma unroll
        for (int ks = 0; ks < 2; ks++) {
            unsigned ah[4][4], al[4][4], bh[2][4], bl[2][4];
#pragma unroll
            for (int mf = 0; mf < 4; mf++) {
                int row = warp_m + mf * 16 + arow;
                int c = ks * 2 + aoff;
                unsigned off = row * 64 + (((c + (row >> 1)) & 3) << 4);
                ldm4(aH + off, ah[mf][0], ah[mf][1], ah[mf][2], ah[mf][3]);
                ldm4(aL + off, al[mf][0], al[mf][1], al[mf][2], al[mf][3]);
            }
#pragma unroll
            for (int p = 0; p < 2; p++) {
                int row = warp_n + p * 16 + brow;
                int c = ks * 2 + boff;
                unsigned off = row * 64 + (((c + (row >> 1)) & 3) << 4);
                ldm4(bH + off, bh[p][0], bh[p][1], bh[p][2], bh[p][3]);
                ldm4(bL + off, bl[p][0], bl[p][1], bl[p][2], bl[p][3]);
            }
#pragma unroll
            for (int mf = 0; mf < 4; mf++)
#pragma unroll
                for (int p = 0; p < 2; p++) {
                    mma16816(acc[mf][2 * p],     ah[mf], bh[p][0], bh[p][1]);
                    mma16816(acc[mf][2 * p],     ah[mf], bl[p][0], bl[p][1]);
                    mma16816(acc[mf][2 * p],     al[mf], bh[p][0], bh[p][1]);
                    mma16816(acc[mf][2 * p + 1], ah[mf], bh[p][2], bh[p][3]);
                    mma16816(acc[mf][2 * p + 1], ah[mf], bl[p][2], bl[p][3]);
                    mma16816(acc[mf][2 * p + 1], al[mf], bh[p][2], bh[p][3]);
                }
        }
        __syncthreads();
    }

    float* Cb; int Nld, coff;
    if (n0 < nsplit) { Cb = C0; Nld = Nld0; coff = n0; }
    else             { Cb = C1; Nld = Nld1; coff = n0 - nsplit; }

#pragma unroll
    for (int mf = 0; mf < 4; mf++)
#pragma unroll
        for (int nf = 0; nf < 4; nf++) {
            int row = m0 + warp_m + mf * 16 + (lane >> 2);
            int col = coff + warp_n + nf * 8 + (lane & 3) * 2;
            *reinterpret_cast<float2*>(&Cb[(size_t)row * Nld + col]) =
                make_float2(acc[mf][nf][0], acc[mf][nf][1]);
            *reinterpret_cast<float2*>(&Cb[(size_t)(row + 8) * Nld + col]) =
                make_float2(acc[mf][nf][2], acc[mf][nf][3]);
        }
}

// ---------------------------------------------------------------------------
// Fused L2-norm + RoPE + hi/lo split. 8 warps/block, one (t,unit) per warp.
// ---------------------------------------------------------------------------
__global__ __launch_bounds__(256)
void norm_rope_split(const float* __restrict__ q, const float* __restrict__ kv,
                     __nv_bfloat16* __restrict__ qh, __nv_bfloat16* __restrict__ ql,
                     __nv_bfloat16* __restrict__ kvh, __nv_bfloat16* __restrict__ kvl)
{
    const int gw = blockIdx.x * 8 + (threadIdx.x >> 5);
    const int lane = threadIdx.x & 31;
    const int t = gw >> 5;
    const int u = gw & 31;
    if (u >= 24) return;

    if (u < 20) {
        const float* src;
        __nv_bfloat16 *dh, *dl;
        size_t off;
        if (u < HEADS) {
            off = (size_t)t * C_DIM + u * HDIM;
            src = q + off; dh = qh + off; dl = ql + off;
        } else {
            off = (size_t)t * KV_DIM + (u - HEADS) * HDIM;
            src = kv + off; dh = kvh + off; dl = kvl + off;
        }
        float a = src[lane];
        float b = src[lane + 32];
        float ss = a * a + b * b;
#pragma unroll
        for (int o = 16; o > 0; o >>= 1)
            ss += __shfl_xor_sync(0xffffffffu, ss, o);
        float inv = 1.f / (sqrtf(ss) + 1e-6f);

        float theta = exp2f(-(float)lane * 0.41524101186092f);
        float ang = (float)t * theta;
        float sv, cv;
        sincosf(ang, &sv, &cv);

        float v0 = (a * cv - b * sv) * inv;
        float v1 = (b * cv + a * sv) * inv;
        __nv_bfloat16 h0 = __float2bfloat16(v0);
        __nv_bfloat16 h1 = __float2bfloat16(v1);
        dh[lane]      = h0;
        dh[lane + 32] = h1;
        dl[lane]      = __float2bfloat16(v0 - __bfloat162float(h0));
        dl[lane + 32] = __float2bfloat16(v1 - __bfloat162float(h1));
    } else {
        size_t off = (size_t)t * KV_DIM + 256 + (u - 20) * HDIM;
        const float* src = kv + off;
#pragma unroll
        for (int j = 0; j < 2; j++) {
            float v = src[lane + 32 * j];
            __nv_bfloat16 hh = __float2bfloat16(v);
            kvh[off + lane + 32 * j] = hh;
            kvl[off + lane + 32 * j] = __float2bfloat16(v - __bfloat162float(hh));
        }
    }
}

// ---------------------------------------------------------------------------
// HMMA windowed flash attention, double-buffered K/V; long-window CTAs first.
// ---------------------------------------------------------------------------
#define KV_STAGE_BYTES 32768

__global__ __launch_bounds__(128, 2)
void attn_tc(const __nv_bfloat16* __restrict__ qh, const __nv_bfloat16* __restrict__ ql,
             const __nv_bfloat16* __restrict__ kvh, const __nv_bfloat16* __restrict__ kvl,
             __nv_bfloat16* __restrict__ yh, __nv_bfloat16* __restrict__ yl)
{
    __shared__ __align__(16) __nv_bfloat16 sQH[4096], sQL[4096];
    extern __shared__ __align__(16) unsigned char kvsmem[];
    const unsigned kvbase = smem_u32(kvsmem);

    const int mt = (T_SEQ / 64 - 1) - blockIdx.x;   // big windows launch first
    const int h = blockIdx.y;
    const int kvhead = h >> 2;
    const int m0 = mt * 64;
    const int tid = threadIdx.x, lane = tid & 31, w = tid >> 5;

    const unsigned uQH = smem_u32(sQH), uQL = smem_u32(sQL);

#pragma unroll
    for (int i = 0; i < 8; i++) {
        int idx = tid + i * 128;
        int buf = idx >> 9, e = idx & 511;
        int r = e >> 3, c = e & 7;
        const __nv_bfloat16* src =
            (buf ? ql : qh) + (size_t)(m0 + r) * C_DIM + h * HDIM + c * 8;
        unsigned dst = (buf ? uQL : uQH) + r * 128 + (((c ^ (r & 7))) << 4);
        cp_async16(dst, src);
    }

    auto fill_kv = [&](int nt, unsigned bufbase) {
        const int n0 = nt * 64;
#pragma unroll
        for (int i = 0; i < 16; i++) {
            int idx = tid + i * 128;
            int tile = idx >> 9;
            int e = idx & 511;
            int r = e >> 3, c = e & 7;
            const __nv_bfloat16* base = (tile & 1) ? kvl : kvh;
            int coloff = (tile < 2) ? (kvhead * HDIM) : (256 + kvhead * HDIM);
            const __nv_bfloat16* src = base + (size_t)(n0 + r) * KV_DIM + coloff + c * 8;
            cp_async16(bufbase + tile * 8192 + r * 128 + (((c ^ (r & 7))) << 4), src);
        }
        asm volatile("cp.async.commit_group;\n" ::: "memory");
    };

    float o[8][4];
    float m_i[2], l_i[2];
#pragma unroll
    for (int nf = 0; nf < 8; nf++)
#pragma unroll
        for (int r = 0; r < 4; r++) o[nf][r] = 0.f;
    m_i[0] = m_i[1] = -1e30f;
    l_i[0] = l_i[1] = 0.f;

    const int arow = lane & 15, aoff = lane >> 4;
    const int brow = (lane & 7) + ((lane >> 4) << 3);
    const int boff = (lane >> 3) & 1;
    const int vrow = (lane & 7) + (((lane >> 3) & 1) << 3);
    const int voff = lane >> 4;

    const int nstart = (mt >= 8) ? (mt - 8) : 0;
    fill_kv(nstart, kvbase);

    for (int nt = nstart; nt <= mt; nt++) {
        const int n0 = nt * 64;
        const int cb = (nt - nstart) & 1;
        const unsigned cur = kvbase + cb * KV_STAGE_BYTES;

        __syncthreads();
        if (nt + 1 <= mt) {
            fill_kv(nt + 1, kvbase + (cb ^ 1) * KV_STAGE_BYTES);
            asm volatile("cp.async.wait_group 1;\n" ::: "memory");
        } else {
            asm volatile("cp.async.wait_group 0;\n" ::: "memory");
        }
        __syncthreads();

        const unsigned uKH = cur, uKL = cur + 8192, uVH = cur + 16384, uVL = cur + 24576;

        float s[8][4];
#pragma unroll
        for (int nf = 0; nf < 8; nf++)
#pragma unroll
            for (int r = 0; r < 4; r++) s[nf][r] = 0.f;

#pragma unroll
        for (int ks = 0; ks < 4; ks++) {
            unsigned ah[4], al[4];
            int ar = 16 * w + arow;
            int ac = ks * 2 + aoff;
            unsigned aaddr = ar * 128 + (((ac ^ (ar & 7))) << 4);
            ldm4(uQH + aaddr, ah[0], ah[1], ah[2], ah[3]);
            ldm4(uQL + aaddr, al[0], al[1], al[2], al[3]);
#pragma unroll
            for (int p = 0; p < 4; p++) {
                unsigned bh[4], bl[4];
                int br = p * 16 + brow;
                int bc = ks * 2 + boff;
                unsigned baddr = br * 128 + (((bc ^ (br & 7))) << 4);
                ldm4(uKH + baddr, bh[0], bh[1], bh[2], bh[3]);
                ldm4(uKL + baddr, bl[0], bl[1], bl[2], bl[3]);
                mma16816(s[2 * p],     ah, bh[0], bh[1]);
                mma16816(s[2 * p],     ah, bl[0], bl[1]);
                mma16816(s[2 * p],     al, bh[0], bh[1]);
                mma16816(s[2 * p + 1], ah, bh[2], bh[3]);
                mma16816(s[2 * p + 1], ah, bl[2], bl[3]);
                mma16816(s[2 * p + 1], al, bh[2], bh[3]);
            }
        }

        const bool needmask = (nt == mt) || (nt == mt - 8);
        const int r0 = m0 + 16 * w + (lane >> 2);
        const int cbase = n0 + 2 * (lane & 3);
#pragma unroll
        for (int nf = 0; nf < 8; nf++)
#pragma unroll
            for (int r = 0; r < 4; r++) {
                float v = s[nf][r] * 0.125f;
                if (needmask) {
                    int qr = r0 + 8 * (r >> 1);
                    int kc = cbase + 8 * nf + (r & 1);
                    if (kc > qr || kc <= qr - WINDOW_SZ) v = -1e30f;
                }
                s[nf][r] = v;
            }

#pragma unroll
        for (int j = 0; j < 2; j++) {
            float tmax = -1e30f;
#pragma unroll
            for (int nf = 0; nf < 8; nf++)
                tmax = fmaxf(tmax, fmaxf(s[nf][2 * j], s[nf][2 * j + 1]));
            tmax = fmaxf(tmax, __shfl_xor_sync(0xffffffffu, tmax, 1));
            tmax = fmaxf(tmax, __shfl_xor_sync(0xffffffffu, tmax, 2));
            float mn = fmaxf(m_i[j], tmax);
            float corr = __expf(m_i[j] - mn);
            m_i[j] = mn;
            float rsum = 0.f;
#pragma unroll
            for (int nf = 0; nf < 8; nf++) {
                float p0 = __expf(s[nf][2 * j] - mn);
                float p1 = __expf(s[nf][2 * j + 1] - mn);
                s[nf][2 * j] = p0;
                s[nf][2 * j + 1] = p1;
                rsum += p0 + p1;
            }
            rsum += __shfl_xor_sync(0xffffffffu, rsum, 1);
            rsum += __shfl_xor_sync(0xffffffffu, rsum, 2);
            l_i[j] = l_i[j] * corr + rsum;
#pragma unroll
            for (int nf = 0; nf < 8; nf++) {
                o[nf][2 * j]     *= corr;
                o[nf][2 * j + 1] *= corr;
            }
        }

#pragma unroll
        for (int kc = 0; kc < 4; kc++) {
            unsigned aph[4], apl[4];
            split2(s[2 * kc][0],     s[2 * kc][1],     aph[0], apl[0]);
            split2(s[2 * kc][2],     s[2 * kc][3],     aph[1], apl[1]);
            split2(s[2 * kc + 1][0], s[2 * kc + 1][1], aph[2], apl[2]);
            split2(s[2 * kc + 1][2], s[2 * kc + 1][3], aph[3], apl[3]);
            int krow = kc * 16 + vrow;
#pragma unroll
            for (int nfb = 0; nfb < 8; nfb += 2) {
                unsigned vh[4], vl[4];
                int chunk = nfb + voff;
                unsigned vaddr = krow * 128 + (((chunk ^ (krow & 7))) << 4);
                ldm4t(uVH + vaddr, vh[0], vh[1], vh[2], vh[3]);
                ldm4t(uVL + vaddr, vl[0], vl[1], vl[2], vl[3]);
                mma16816(o[nfb],     aph, vh[0], vh[1]);
                mma16816(o[nfb],     aph, vl[0], vl[1]);
                mma16816(o[nfb],     apl, vh[0], vh[1]);
                mma16816(o[nfb + 1], aph, vh[2], vh[3]);
                mma16816(o[nfb + 1], aph, vl[2], vl[3]);
                mma16816(o[nfb + 1], apl, vh[2], vh[3]);
            }
        }
    }

    float inv0 = 1.f / l_i[0], inv1 = 1.f / l_i[1];
#pragma unroll
    for (int nf = 0; nf < 8; nf++) {
        int col = h * HDIM + 8 * nf + 2 * (lane & 3);
#pragma unroll
        for (int j = 0; j < 2; j++) {
            int row = m0 + 16 * w + (lane >> 2) + 8 * j;
            float inv = j ? inv1 : inv0;
            float v0 = o[nf][2 * j] * inv, v1 = o[nf][2 * j + 1] * inv;
            unsigned hi, lo;
            split2(v0, v1, hi, lo);
            *reinterpret_cast<unsigned*>(&yh[(size_t)row * C_DIM + col]) = hi;
            *reinterpret_cast<unsigned*>(&yl[(size_t)row * C_DIM + col]) = lo;
        }
    }
}

// ---------------------------------------------------------------------------
extern "C" void kernel_launch(void* const* d_in, const int* in_sizes, int n_in,
                              void* d_out, int out_size)
{
    const float* x     = (const float*)d_in[0];
    const float* Wq    = (const float*)d_in[1];
    const float* Wkv   = (const float*)d_in[2];
    const float* Wproj = (const float*)d_in[3];
    float* out = (float*)d_out;

    float *gq, *gkv;
    cudaGetSymbolAddress((void**)&gq, g_q);
    cudaGetSymbolAddress((void**)&gkv, g_kv);

    __nv_bfloat16 *xh, *xl, *wqkh, *wqkl, *wph, *wpl, *yh, *yl;
    __nv_bfloat16 *qh, *ql, *kvh, *kvl;
    cudaGetSymbolAddress((void**)&xh, g_xh);     cudaGetSymbolAddress((void**)&xl, g_xl);
    cudaGetSymbolAddress((void**)&wqkh, g_wqkh); cudaGetSymbolAddress((void**)&wqkl, g_wqkl);
    cudaGetSymbolAddress((void**)&wph, g_wph);   cudaGetSymbolAddress((void**)&wpl, g_wpl);
    cudaGetSymbolAddress((void**)&yh, g_yh);     cudaGetSymbolAddress((void**)&yl, g_yl);
    cudaGetSymbolAddress((void**)&qh, g_qh);     cudaGetSymbolAddress((void**)&ql, g_ql);
    cudaGetSymbolAddress((void**)&kvh, g_kvh);   cudaGetSymbolAddress((void**)&kvl, g_kvl);

    static bool attr_set = false;
    if (!attr_set) {
        cudaFuncSetAttribute(gemm_tc, cudaFuncAttributeMaxDynamicSharedMemorySize,
                             3 * CHUNK_BYTES);
        cudaFuncSetAttribute(attn_tc, cudaFuncAttributeMaxDynamicSharedMemorySize,
                             2 * KV_STAGE_BYTES);
        attr_set = true;
    }

    const int nx4 = T_SEQ * C_DIM / 4;
    const int nq4 = C_DIM * C_DIM / 4;
    const int nk4 = KV_DIM * C_DIM / 4;
    const int ntot4 = nx4 + 2 * nq4 + nk4;

    // single launch, 2 float4/thread
    cvt_split4<<<(ntot4 / 2 + 255) / 256, 256>>>(
        x, xh, xl, nx4,
        Wq, wqkh, wqkl, nq4,
        Wkv, wqkh + (size_t)C_DIM * C_DIM, wqkl + (size_t)C_DIM * C_DIM, nk4,
        Wproj, wph, wpl, nq4);

    // Fused [Q | KV] = x @ [Wq; Wkv]^T : N = 1536, 192 CTAs
    gemm_tc<<<dim3(1536 / 128, T_SEQ / 128), 256, 3 * CHUNK_BYTES>>>(
        xh, xl, wqkh, wqkl, gq, gkv, C_DIM, C_DIM, KV_DIM);

    norm_rope_split<<<T_SEQ * 32 / 8, 256>>>(gq, gkv, qh, ql, kvh, kvl);

    attn_tc<<<dim3(T_SEQ / 64, HEADS), 128, 2 * KV_STAGE_BYTES>>>(
        qh, ql, kvh, kvl, yh, yl);

    // out = y @ Wproj^T
    gemm_tc<<<dim3(C_DIM / 128, T_SEQ / 128), 256, 3 * CHUNK_BYTES>>>(
        yh, yl, wph, wpl, out, nullptr, 1 << 30, C_DIM, 0);
}